// round 9
// baseline (speedup 1.0000x reference)
#include <cuda_runtime.h>
#include <cuda_bf16.h>
#include <cstdint>

#define B_ 2
#define N_ 2048
#define C_ 1024
#define H_ 16
#define D_ 64

// ------------------------- scratch (__device__ globals) ----------------------
__device__ float g_Q[(size_t)B_*H_*N_*D_];   // tf32-rounded, pre-scaled by 1/8
__device__ float g_K[(size_t)B_*H_*N_*D_];   // tf32-rounded
__device__ float g_V[(size_t)B_*H_*N_*D_];   // tf32-rounded
__device__ float g_O[(size_t)B_*N_*C_];      // attention output f32

__device__ __nv_bfloat16 g_Xs[2u*4096u*1024u];    // x   split: hi plane, lo plane
__device__ __nv_bfloat16 g_Cs[2u*4096u*1024u];    // ctx split
__device__ __nv_bfloat16 g_Os[2u*4096u*1024u];    // attn-out split
__device__ __nv_bfloat16 g_Ws[4u*2u*1024u*1024u]; // 4 weights x (hi, lo)

// ------------------------------- PTX helpers --------------------------------
__device__ __forceinline__ unsigned f2tf32(float f) {
    unsigned o; asm("cvt.rna.tf32.f32 %0, %1;" : "=r"(o) : "f"(f)); return o;
}
__device__ __forceinline__ void mma_tf32(float c[4], const unsigned a[4],
                                         unsigned b0, unsigned b1) {
    asm volatile("mma.sync.aligned.m16n8k8.row.col.f32.tf32.tf32.f32 "
        "{%0,%1,%2,%3}, {%4,%5,%6,%7}, {%8,%9}, {%0,%1,%2,%3};"
        : "+f"(c[0]), "+f"(c[1]), "+f"(c[2]), "+f"(c[3])
        : "r"(a[0]), "r"(a[1]), "r"(a[2]), "r"(a[3]), "r"(b0), "r"(b1));
}
__device__ __forceinline__ void mma_bf16(float c[4], const unsigned a[4],
                                         unsigned b0, unsigned b1) {
    asm volatile("mma.sync.aligned.m16n8k16.row.col.f32.bf16.bf16.f32 "
        "{%0,%1,%2,%3}, {%4,%5,%6,%7}, {%8,%9}, {%0,%1,%2,%3};"
        : "+f"(c[0]), "+f"(c[1]), "+f"(c[2]), "+f"(c[3])
        : "r"(a[0]), "r"(a[1]), "r"(a[2]), "r"(a[3]), "r"(b0), "r"(b1));
}
__device__ __forceinline__ void cp16(unsigned dst, const void* src) {
    asm volatile("cp.async.cg.shared.global [%0], [%1], 16;" :: "r"(dst), "l"(src));
}
#define CP_COMMIT() asm volatile("cp.async.commit_group;")
#define CP_WAIT1()  asm volatile("cp.async.wait_group 1;")
#define CP_WAIT0()  asm volatile("cp.async.wait_group 0;")
__device__ __forceinline__ unsigned s_u32(const void* p) {
    return (unsigned)__cvta_generic_to_shared(p);
}

// -------------------------- bf16 hi/lo split kernel -------------------------
__global__ __launch_bounds__(256)
void split_kernel(const float* __restrict__ in, __nv_bfloat16* __restrict__ outp,
                  int n4)
{
    int i = blockIdx.x * 256 + threadIdx.x;
    if (i >= n4) return;
    float4 v = reinterpret_cast<const float4*>(in)[i];
    __nv_bfloat16 h0 = __float2bfloat16_rn(v.x);
    __nv_bfloat16 h1 = __float2bfloat16_rn(v.y);
    __nv_bfloat16 h2 = __float2bfloat16_rn(v.z);
    __nv_bfloat16 h3 = __float2bfloat16_rn(v.w);
    __nv_bfloat16 l0 = __float2bfloat16_rn(v.x - __bfloat162float(h0));
    __nv_bfloat16 l1 = __float2bfloat16_rn(v.y - __bfloat162float(h1));
    __nv_bfloat16 l2 = __float2bfloat16_rn(v.z - __bfloat162float(h2));
    __nv_bfloat16 l3 = __float2bfloat16_rn(v.w - __bfloat162float(h3));
    __nv_bfloat162* hi2 = reinterpret_cast<__nv_bfloat162*>(outp);
    __nv_bfloat162* lo2 = reinterpret_cast<__nv_bfloat162*>(outp + (size_t)n4 * 4);
    hi2[2*i+0] = __halves2bfloat162(h0, h1);
    hi2[2*i+1] = __halves2bfloat162(h2, h3);
    lo2[2*i+0] = __halves2bfloat162(l0, l1);
    lo2[2*i+1] = __halves2bfloat162(l2, l3);
}

// ---------------------- bf16 3-term split GEMM (proj) -----------------------
// out[M=4096, 1024] = X @ W^T + bias.  X/W pre-split into bf16 hi/lo planes.
// Block: 256 thr (8 warps: 4m x 2n), tile 128x64, BK=32, cp.async 2 stages.
// smem per stage (uint words): A [2pl][128][20] = 5120, B [2pl][64][20] = 2560.
template<bool HEAD_MAJOR, bool ROUND>
__global__ __launch_bounds__(256, 2)
void proj_bf16_kernel(const __nv_bfloat16* __restrict__ A,
                      const __nv_bfloat16* __restrict__ W,
                      const float* __restrict__ bias,
                      float* __restrict__ out, float oscale)
{
    extern __shared__ __align__(16) unsigned sm32[];
    const int tid  = threadIdx.x;
    const int lane = tid & 31, warp = tid >> 5;
    const int wm   = (warp >> 1) * 32, wn = (warp & 1) * 32;
    const int g    = lane >> 2, j = lane & 3;
    const int m0   = blockIdx.y * 128, j0 = blockIdx.x * 64;

    const __nv_bfloat16* Apl0 = A;
    const __nv_bfloat16* Apl1 = A + (size_t)4096 * 1024;
    const __nv_bfloat16* Wpl0 = W;
    const __nv_bfloat16* Wpl1 = W + (size_t)1024 * 1024;
    const unsigned sbase = s_u32(sm32);

    float acc[2][4][4];
    #pragma unroll
    for (int a = 0; a < 2; a++)
        #pragma unroll
        for (int b = 0; b < 4; b++)
            #pragma unroll
            for (int c = 0; c < 4; c++) acc[a][b][c] = 0.0f;

    auto issue_tile = [&](int kt, int stg) {
        unsigned base = sbase + (unsigned)stg * 7680u * 4u;
        #pragma unroll
        for (int i = 0; i < 4; i++) {                 // A: 1024 x 16B
            int c  = tid + i * 256;
            int pl = c >> 9, rem = c & 511, r = rem >> 2, q = rem & 3;
            const __nv_bfloat16* src = (pl ? Apl1 : Apl0) +
                (size_t)(m0 + r) * 1024 + kt + q * 8;
            cp16(base + (unsigned)(pl * 2560 + r * 20 + q * 4) * 4u, src);
        }
        #pragma unroll
        for (int i = 0; i < 2; i++) {                 // B: 512 x 16B
            int c  = tid + i * 256;
            int pl = c >> 8, rem = c & 255, r = rem >> 2, q = rem & 3;
            const __nv_bfloat16* src = (pl ? Wpl1 : Wpl0) +
                (size_t)(j0 + r) * 1024 + kt + q * 8;
            cp16(base + (unsigned)(5120 + pl * 1280 + r * 20 + q * 4) * 4u, src);
        }
    };

    issue_tile(0, 0);
    CP_COMMIT();

    for (int t = 0; t < 32; t++) {
        if (t + 1 < 32) { issue_tile((t + 1) * 32, (t + 1) & 1); CP_COMMIT(); CP_WAIT1(); }
        else            { CP_WAIT0(); }
        __syncthreads();

        const unsigned* S = sm32 + (t & 1) * 7680;
        #pragma unroll
        for (int ks = 0; ks < 2; ks++) {
            unsigned ah[2][4], al[2][4], bh[4][2], bl[4][2];
            #pragma unroll
            for (int mf = 0; mf < 2; mf++) {
                int rb = (wm + mf * 16 + g) * 20 + ks * 8 + j;
                ah[mf][0] = S[rb];            ah[mf][1] = S[rb + 160];
                ah[mf][2] = S[rb + 4];        ah[mf][3] = S[rb + 164];
                al[mf][0] = S[2560 + rb];     al[mf][1] = S[2560 + rb + 160];
                al[mf][2] = S[2560 + rb + 4]; al[mf][3] = S[2560 + rb + 164];
            }
            #pragma unroll
            for (int nf = 0; nf < 4; nf++) {
                int rb = 5120 + (wn + nf * 8 + g) * 20 + ks * 8 + j;
                bh[nf][0] = S[rb];        bh[nf][1] = S[rb + 4];
                bl[nf][0] = S[rb + 1280]; bl[nf][1] = S[rb + 1284];
            }
            #pragma unroll
            for (int mf = 0; mf < 2; mf++)
                #pragma unroll
                for (int nf = 0; nf < 4; nf++) {
                    mma_bf16(acc[mf][nf], ah[mf], bh[nf][0], bh[nf][1]);
                    mma_bf16(acc[mf][nf], ah[mf], bl[nf][0], bl[nf][1]);
                    mma_bf16(acc[mf][nf], al[mf], bh[nf][0], bh[nf][1]);
                }
        }
        __syncthreads();
    }

    #pragma unroll
    for (int mf = 0; mf < 2; mf++) {
        #pragma unroll
        for (int e = 0; e < 2; e++) {
            int row = m0 + wm + mf * 16 + g + e * 8;
            #pragma unroll
            for (int nf = 0; nf < 4; nf++) {
                int col = j0 + wn + nf * 8 + 2 * j;
                float v0 = (acc[mf][nf][e * 2 + 0] + bias[col])     * oscale;
                float v1 = (acc[mf][nf][e * 2 + 1] + bias[col + 1]) * oscale;
                if (ROUND) {
                    v0 = __uint_as_float(f2tf32(v0));
                    v1 = __uint_as_float(f2tf32(v1));
                }
                float2 val = make_float2(v0, v1);
                if (HEAD_MAJOR) {
                    int bb = row >> 11, n = row & (N_ - 1);
                    int d  = col - j0;
                    *reinterpret_cast<float2*>(
                        &out[(((size_t)bb * H_ + blockIdx.x) * N_ + n) * 64 + d]) = val;
                } else {
                    *reinterpret_cast<float2*>(&out[(size_t)row * 1024 + col]) = val;
                }
            }
        }
    }
}

// --------------------- register-resident flash attention --------------------
// Block 128 thr (4 warps), q-tile 64 (warp owns 16 rows), key-tile 64.
// smem floats: Ks[2][64][68] @0 | Vs[2][64][72] @8704 | Ps[4][16][68] @17920.
__global__ __launch_bounds__(128, 2)
void attn_kernel(const float* __restrict__ Qg, const float* __restrict__ Kg,
                 const float* __restrict__ Vg, const float* __restrict__ bias,
                 float* __restrict__ Og)
{
    extern __shared__ __align__(16) float sf[];
    const int tid  = threadIdx.x;
    const int lane = tid & 31, warp = tid >> 5;
    const int g    = lane >> 2, j = lane & 3;
    const int q0   = blockIdx.x * 64, h = blockIdx.y, b = blockIdx.z;
    const size_t bh = ((size_t)b * H_ + h) * N_;
    const int wq   = warp * 16;
    float* Psw = sf + 17920 + warp * 1088;
    const unsigned sbase = s_u32(sf);

    // Q fragments (tf32-rounded & pre-scaled by 1/8 in proj epilogue)
    unsigned qa[8][4];
    {
        const float* q0p = Qg + (bh + q0 + wq + g) * 64;
        const float* q1p = q0p + 8 * 64;
        #pragma unroll
        for (int dk = 0; dk < 8; dk++) {
            qa[dk][0] = __float_as_uint(q0p[dk * 8 + j]);
            qa[dk][1] = __float_as_uint(q1p[dk * 8 + j]);
            qa[dk][2] = __float_as_uint(q0p[dk * 8 + j + 4]);
            qa[dk][3] = __float_as_uint(q1p[dk * 8 + j + 4]);
        }
    }

    float Oa[8][4];
    #pragma unroll
    for (int nb = 0; nb < 8; nb++)
        #pragma unroll
        for (int e = 0; e < 4; e++) Oa[nb][e] = 0.0f;
    float m0r = -1e30f, m1r = -1e30f, l0 = 0.0f, l1 = 0.0f;

    auto issue_kv = [&](int k0, int stg) {
        unsigned kbase = sbase + (unsigned)(stg * 4352) * 4u;
        unsigned vbase = sbase + (unsigned)(8704 + stg * 4608) * 4u;
        const float* Kp = Kg + (bh + k0) * 64;
        const float* Vp = Vg + (bh + k0) * 64;
        #pragma unroll
        for (int i = 0; i < 8; i++) {
            int c = tid + i * 128;
            int r = c >> 4, cc = (c & 15) * 4;
            cp16(kbase + (unsigned)(r * 68 + cc) * 4u, Kp + r * 64 + cc);
            cp16(vbase + (unsigned)(r * 72 + cc) * 4u, Vp + r * 64 + cc);
        }
    };

    issue_kv(0, 0);
    CP_COMMIT();

    const float* bb0 = bias + ((size_t)h * N_ + q0 + wq + g) * N_;
    const float* bb1 = bb0 + (size_t)8 * N_;

    for (int t = 0; t < 32; t++) {
        if (t + 1 < 32) { issue_kv((t + 1) * 64, (t + 1) & 1); CP_COMMIT(); CP_WAIT1(); }
        else            { CP_WAIT0(); }
        __syncthreads();

        const float* Ks = sf + (t & 1) * 4352;
        const float* Vs = sf + 8704 + (t & 1) * 4608;

        // S = Q @ K^T
        float sa[8][4];
        #pragma unroll
        for (int nb = 0; nb < 8; nb++)
            #pragma unroll
            for (int e = 0; e < 4; e++) sa[nb][e] = 0.0f;
        #pragma unroll
        for (int dk = 0; dk < 8; dk++)
            #pragma unroll
            for (int nb = 0; nb < 8; nb++) {
                const float* kp = Ks + (nb * 8 + g) * 68 + dk * 8 + j;
                mma_tf32(sa[nb], qa[dk], __float_as_uint(kp[0]),
                                         __float_as_uint(kp[4]));
            }

        // bias + online softmax (register stats)
        const int kcol = t * 64;
        float mx0 = -1e30f, mx1 = -1e30f;
        #pragma unroll
        for (int nb = 0; nb < 8; nb++) {
            float2 t0 = *reinterpret_cast<const float2*>(bb0 + kcol + nb * 8 + 2 * j);
            float2 t1 = *reinterpret_cast<const float2*>(bb1 + kcol + nb * 8 + 2 * j);
            sa[nb][0] += t0.x; sa[nb][1] += t0.y;
            sa[nb][2] += t1.x; sa[nb][3] += t1.y;
            mx0 = fmaxf(mx0, fmaxf(sa[nb][0], sa[nb][1]));
            mx1 = fmaxf(mx1, fmaxf(sa[nb][2], sa[nb][3]));
        }
        mx0 = fmaxf(mx0, __shfl_xor_sync(0xffffffffu, mx0, 1));
        mx0 = fmaxf(mx0, __shfl_xor_sync(0xffffffffu, mx0, 2));
        mx1 = fmaxf(mx1, __shfl_xor_sync(0xffffffffu, mx1, 1));
        mx1 = fmaxf(mx1, __shfl_xor_sync(0xffffffffu, mx1, 2));
        float mn0 = fmaxf(m0r, mx0), mn1 = fmaxf(m1r, mx1);
        float al0 = __expf(m0r - mn0), al1 = __expf(m1r - mn1);
        m0r = mn0; m1r = mn1;

        __syncwarp();
        float s0 = 0.0f, s1 = 0.0f;
        #pragma unroll
        for (int nb = 0; nb < 8; nb++) {
            float p0 = __expf(sa[nb][0] - mn0);
            float p1 = __expf(sa[nb][1] - mn0);
            float p2 = __expf(sa[nb][2] - mn1);
            float p3 = __expf(sa[nb][3] - mn1);
            s0 += p0 + p1; s1 += p2 + p3;
            Psw[g * 68 + nb * 8 + 2 * j]           = __uint_as_float(f2tf32(p0));
            Psw[g * 68 + nb * 8 + 2 * j + 1]       = __uint_as_float(f2tf32(p1));
            Psw[(g + 8) * 68 + nb * 8 + 2 * j]     = __uint_as_float(f2tf32(p2));
            Psw[(g + 8) * 68 + nb * 8 + 2 * j + 1] = __uint_as_float(f2tf32(p3));
            Oa[nb][0] *= al0; Oa[nb][1] *= al0;
            Oa[nb][2] *= al1; Oa[nb][3] *= al1;
        }
        s0 += __shfl_xor_sync(0xffffffffu, s0, 1);
        s0 += __shfl_xor_sync(0xffffffffu, s0, 2);
        s1 += __shfl_xor_sync(0xffffffffu, s1, 1);
        s1 += __shfl_xor_sync(0xffffffffu, s1, 2);
        l0 = l0 * al0 + s0;
        l1 = l1 * al1 + s1;
        __syncwarp();

        // O += P @ V
        #pragma unroll
        for (int kk = 0; kk < 8; kk++) {
            unsigned pa[4];
            pa[0] = __float_as_uint(Psw[g * 68 + kk * 8 + j]);
            pa[1] = __float_as_uint(Psw[(g + 8) * 68 + kk * 8 + j]);
            pa[2] = __float_as_uint(Psw[g * 68 + kk * 8 + j + 4]);
            pa[3] = __float_as_uint(Psw[(g + 8) * 68 + kk * 8 + j + 4]);
            #pragma unroll
            for (int nb = 0; nb < 8; nb++) {
                const float* vp = Vs + (kk * 8 + j) * 72 + nb * 8 + g;
                mma_tf32(Oa[nb], pa, __float_as_uint(vp[0]),
                                     __float_as_uint(vp[4 * 72]));
            }
        }
        __syncthreads();  // release this K/V stage before it is overwritten
    }

    const float li0 = 1.0f / l0, li1 = 1.0f / l1;
    const size_t o0 = ((size_t)b * N_ + q0 + wq + g) * C_ + (size_t)h * 64;
    const size_t o1 = o0 + (size_t)8 * C_;
    #pragma unroll
    for (int nb = 0; nb < 8; nb++) {
        *reinterpret_cast<float2*>(&Og[o0 + nb * 8 + 2 * j]) =
            make_float2(Oa[nb][0] * li0, Oa[nb][1] * li0);
        *reinterpret_cast<float2*>(&Og[o1 + nb * 8 + 2 * j]) =
            make_float2(Oa[nb][2] * li1, Oa[nb][3] * li1);
    }
}

// --------------------------------- launcher ---------------------------------
extern "C" void kernel_launch(void* const* d_in, const int* in_sizes, int n_in,
                              void* d_out, int out_size)
{
    (void)in_sizes; (void)n_in; (void)out_size;
    const float* x    = (const float*)d_in[0];
    const float* ctx  = (const float*)d_in[1];
    const float* bias = (const float*)d_in[2];
    const float* Wq   = (const float*)d_in[3];
    const float* bq   = (const float*)d_in[4];
    const float* Wk   = (const float*)d_in[5];
    const float* bk   = (const float*)d_in[6];
    const float* Wv   = (const float*)d_in[7];
    const float* bv   = (const float*)d_in[8];
    const float* Wo   = (const float*)d_in[9];
    const float* bo   = (const float*)d_in[10];
    float* out = (float*)d_out;

    float *qp, *kp, *vp, *op;
    __nv_bfloat16 *xs, *cs, *os, *ws;
    cudaGetSymbolAddress((void**)&qp, g_Q);
    cudaGetSymbolAddress((void**)&kp, g_K);
    cudaGetSymbolAddress((void**)&vp, g_V);
    cudaGetSymbolAddress((void**)&op, g_O);
    cudaGetSymbolAddress((void**)&xs, g_Xs);
    cudaGetSymbolAddress((void**)&cs, g_Cs);
    cudaGetSymbolAddress((void**)&os, g_Os);
    cudaGetSymbolAddress((void**)&ws, g_Ws);

    const int proj_smem = 7680 * 2 * 4;   // 61,440 B
    const int attn_smem = 22272 * 4;      // 89,088 B
    cudaFuncSetAttribute(proj_bf16_kernel<true , true >,
        cudaFuncAttributeMaxDynamicSharedMemorySize, proj_smem);
    cudaFuncSetAttribute(proj_bf16_kernel<false, false>,
        cudaFuncAttributeMaxDynamicSharedMemorySize, proj_smem);
    cudaFuncSetAttribute(attn_kernel,
        cudaFuncAttributeMaxDynamicSharedMemorySize, attn_smem);

    const size_t WPITCH = (size_t)2 * 1024 * 1024;  // hi+lo plane per weight

    split_kernel<<<4096, 256>>>(x,   xs, 1048576);
    split_kernel<<<4096, 256>>>(ctx, cs, 1048576);
    split_kernel<<<1024, 256>>>(Wq, ws + 0 * WPITCH, 262144);
    split_kernel<<<1024, 256>>>(Wk, ws + 1 * WPITCH, 262144);
    split_kernel<<<1024, 256>>>(Wv, ws + 2 * WPITCH, 262144);
    split_kernel<<<1024, 256>>>(Wo, ws + 3 * WPITCH, 262144);

    dim3 gp(16, 32);   // (C/64, 4096/128)
    proj_bf16_kernel<true , true ><<<gp, 256, proj_smem>>>(xs, ws + 0 * WPITCH, bq, qp, 0.125f);
    proj_bf16_kernel<true , true ><<<gp, 256, proj_smem>>>(cs, ws + 1 * WPITCH, bk, kp, 1.0f);
    proj_bf16_kernel<true , true ><<<gp, 256, proj_smem>>>(cs, ws + 2 * WPITCH, bv, vp, 1.0f);

    dim3 ga(N_ / 64, H_, B_);   // (32, 16, 2)
    attn_kernel<<<ga, 128, attn_smem>>>(qp, kp, vp, bias, op);

    split_kernel<<<4096, 256>>>(op, os, 1048576);
    proj_bf16_kernel<false, false><<<gp, 256, proj_smem>>>(os, ws + 3 * WPITCH, bo, out, 1.0f);
}

// round 10
// speedup vs baseline: 1.0453x; 1.0453x over previous
#include <cuda_runtime.h>
#include <cuda_bf16.h>
#include <cstdint>

#define B_ 2
#define N_ 2048
#define C_ 1024
#define H_ 16
#define D_ 64

// ------------------------- scratch (__device__ globals) ----------------------
__device__ float g_Q[(size_t)B_*H_*N_*D_];   // tf32-rounded, pre-scaled by 1/8
__device__ float g_K[(size_t)B_*H_*N_*D_];   // tf32-rounded
__device__ float g_V[(size_t)B_*H_*N_*D_];   // tf32-rounded

__device__ __nv_bfloat16 g_Xs[2u*4096u*1024u];    // x   split: hi plane, lo plane
__device__ __nv_bfloat16 g_Cs[2u*4096u*1024u];    // ctx split
__device__ __nv_bfloat16 g_Os[2u*4096u*1024u];    // attn-out split (written by attn)
__device__ __nv_bfloat16 g_Ws[4u*2u*1024u*1024u]; // 4 weights x (hi, lo)

// ------------------------------- PTX helpers --------------------------------
__device__ __forceinline__ unsigned f2tf32(float f) {
    unsigned o; asm("cvt.rna.tf32.f32 %0, %1;" : "=r"(o) : "f"(f)); return o;
}
__device__ __forceinline__ void mma_tf32(float c[4], const unsigned a[4],
                                         unsigned b0, unsigned b1) {
    asm volatile("mma.sync.aligned.m16n8k8.row.col.f32.tf32.tf32.f32 "
        "{%0,%1,%2,%3}, {%4,%5,%6,%7}, {%8,%9}, {%0,%1,%2,%3};"
        : "+f"(c[0]), "+f"(c[1]), "+f"(c[2]), "+f"(c[3])
        : "r"(a[0]), "r"(a[1]), "r"(a[2]), "r"(a[3]), "r"(b0), "r"(b1));
}
__device__ __forceinline__ void mma_bf16(float c[4], const unsigned a[4],
                                         unsigned b0, unsigned b1) {
    asm volatile("mma.sync.aligned.m16n8k16.row.col.f32.bf16.bf16.f32 "
        "{%0,%1,%2,%3}, {%4,%5,%6,%7}, {%8,%9}, {%0,%1,%2,%3};"
        : "+f"(c[0]), "+f"(c[1]), "+f"(c[2]), "+f"(c[3])
        : "r"(a[0]), "r"(a[1]), "r"(a[2]), "r"(a[3]), "r"(b0), "r"(b1));
}
__device__ __forceinline__ void cp16(unsigned dst, const void* src) {
    asm volatile("cp.async.cg.shared.global [%0], [%1], 16;" :: "r"(dst), "l"(src));
}
#define CP_COMMIT() asm volatile("cp.async.commit_group;")
#define CP_WAIT1()  asm volatile("cp.async.wait_group 1;")
#define CP_WAIT0()  asm volatile("cp.async.wait_group 0;")
__device__ __forceinline__ unsigned s_u32(const void* p) {
    return (unsigned)__cvta_generic_to_shared(p);
}

// ----------------------- merged bf16 hi/lo split kernel ---------------------
// One launch splits x, ctx, and the 4 weight matrices.
// Grid: [0,4096) x | [4096,8192) ctx | [8192,12288) weights (1024 blocks each).
__global__ __launch_bounds__(256)
void split_all_kernel(const float* __restrict__ x, const float* __restrict__ ctx,
                      const float* __restrict__ Wq, const float* __restrict__ Wk,
                      const float* __restrict__ Wv, const float* __restrict__ Wo,
                      __nv_bfloat16* __restrict__ xs, __nv_bfloat16* __restrict__ cs,
                      __nv_bfloat16* __restrict__ ws)
{
    int blk = blockIdx.x;
    const float* src;
    __nv_bfloat16* dst;
    int n4;
    if (blk < 4096)      { src = x;   dst = xs; n4 = 1048576; }
    else if (blk < 8192) { src = ctx; dst = cs; n4 = 1048576; blk -= 4096; }
    else {
        int w = (blk - 8192) >> 10;
        blk = (blk - 8192) & 1023;
        n4 = 262144;
        src = (w == 0) ? Wq : (w == 1) ? Wk : (w == 2) ? Wv : Wo;
        dst = ws + (size_t)w * 2097152u;
    }
    int i = blk * 256 + threadIdx.x;
    if (i >= n4) return;
    float4 v = reinterpret_cast<const float4*>(src)[i];
    __nv_bfloat16 h0 = __float2bfloat16_rn(v.x);
    __nv_bfloat16 h1 = __float2bfloat16_rn(v.y);
    __nv_bfloat16 h2 = __float2bfloat16_rn(v.z);
    __nv_bfloat16 h3 = __float2bfloat16_rn(v.w);
    __nv_bfloat16 l0 = __float2bfloat16_rn(v.x - __bfloat162float(h0));
    __nv_bfloat16 l1 = __float2bfloat16_rn(v.y - __bfloat162float(h1));
    __nv_bfloat16 l2 = __float2bfloat16_rn(v.z - __bfloat162float(h2));
    __nv_bfloat16 l3 = __float2bfloat16_rn(v.w - __bfloat162float(h3));
    __nv_bfloat162* hi2 = reinterpret_cast<__nv_bfloat162*>(dst);
    __nv_bfloat162* lo2 = reinterpret_cast<__nv_bfloat162*>(dst + (size_t)n4 * 4);
    hi2[2*i+0] = __halves2bfloat162(h0, h1);
    hi2[2*i+1] = __halves2bfloat162(h2, h3);
    lo2[2*i+0] = __halves2bfloat162(l0, l1);
    lo2[2*i+1] = __halves2bfloat162(l2, l3);
}

// ---------------------- bf16 3-term split GEMM (proj) -----------------------
// out[M=4096, 1024] = A @ W^T + bias.  A/W pre-split into bf16 hi/lo planes.
// Block: 256 thr (8 warps: 4m x 2n), tile 128x64, BK=32, cp.async 2 stages.
// blockIdx.z selects one of up to 3 problem instances (merged Q/K/V).
struct ProjArgs {
    const __nv_bfloat16* A[3];
    const __nv_bfloat16* Wp[3];
    const float* bias[3];
    float* out[3];
    float scale[3];
};

template<bool HEAD_MAJOR, bool ROUND>
__global__ __launch_bounds__(256, 2)
void proj_bf16_kernel(ProjArgs args)
{
    extern __shared__ __align__(16) unsigned sm32[];
    const int z = blockIdx.z;
    const __nv_bfloat16* A = args.A[z];
    const __nv_bfloat16* W = args.Wp[z];
    const float* bias      = args.bias[z];
    float* out             = args.out[z];
    const float oscale     = args.scale[z];

    const int tid  = threadIdx.x;
    const int lane = tid & 31, warp = tid >> 5;
    const int wm   = (warp >> 1) * 32, wn = (warp & 1) * 32;
    const int g    = lane >> 2, j = lane & 3;
    const int m0   = blockIdx.y * 128, j0 = blockIdx.x * 64;

    const __nv_bfloat16* Apl0 = A;
    const __nv_bfloat16* Apl1 = A + (size_t)4096 * 1024;
    const __nv_bfloat16* Wpl0 = W;
    const __nv_bfloat16* Wpl1 = W + (size_t)1024 * 1024;
    const unsigned sbase = s_u32(sm32);

    float acc[2][4][4];
    #pragma unroll
    for (int a = 0; a < 2; a++)
        #pragma unroll
        for (int b = 0; b < 4; b++)
            #pragma unroll
            for (int c = 0; c < 4; c++) acc[a][b][c] = 0.0f;

    auto issue_tile = [&](int kt, int stg) {
        unsigned base = sbase + (unsigned)stg * 7680u * 4u;
        #pragma unroll
        for (int i = 0; i < 4; i++) {                 // A: 1024 x 16B
            int c  = tid + i * 256;
            int pl = c >> 9, rem = c & 511, r = rem >> 2, q = rem & 3;
            const __nv_bfloat16* src = (pl ? Apl1 : Apl0) +
                (size_t)(m0 + r) * 1024 + kt + q * 8;
            cp16(base + (unsigned)(pl * 2560 + r * 20 + q * 4) * 4u, src);
        }
        #pragma unroll
        for (int i = 0; i < 2; i++) {                 // B: 512 x 16B
            int c  = tid + i * 256;
            int pl = c >> 8, rem = c & 255, r = rem >> 2, q = rem & 3;
            const __nv_bfloat16* src = (pl ? Wpl1 : Wpl0) +
                (size_t)(j0 + r) * 1024 + kt + q * 8;
            cp16(base + (unsigned)(5120 + pl * 1280 + r * 20 + q * 4) * 4u, src);
        }
    };

    issue_tile(0, 0);
    CP_COMMIT();

    for (int t = 0; t < 32; t++) {
        if (t + 1 < 32) { issue_tile((t + 1) * 32, (t + 1) & 1); CP_COMMIT(); CP_WAIT1(); }
        else            { CP_WAIT0(); }
        __syncthreads();

        const unsigned* S = sm32 + (t & 1) * 7680;
        #pragma unroll
        for (int ks = 0; ks < 2; ks++) {
            unsigned ah[2][4], al[2][4], bh[4][2], bl[4][2];
            #pragma unroll
            for (int mf = 0; mf < 2; mf++) {
                int rb = (wm + mf * 16 + g) * 20 + ks * 8 + j;
                ah[mf][0] = S[rb];            ah[mf][1] = S[rb + 160];
                ah[mf][2] = S[rb + 4];        ah[mf][3] = S[rb + 164];
                al[mf][0] = S[2560 + rb];     al[mf][1] = S[2560 + rb + 160];
                al[mf][2] = S[2560 + rb + 4]; al[mf][3] = S[2560 + rb + 164];
            }
            #pragma unroll
            for (int nf = 0; nf < 4; nf++) {
                int rb = 5120 + (wn + nf * 8 + g) * 20 + ks * 8 + j;
                bh[nf][0] = S[rb];        bh[nf][1] = S[rb + 4];
                bl[nf][0] = S[rb + 1280]; bl[nf][1] = S[rb + 1284];
            }
            #pragma unroll
            for (int mf = 0; mf < 2; mf++)
                #pragma unroll
                for (int nf = 0; nf < 4; nf++) {
                    mma_bf16(acc[mf][nf], ah[mf], bh[nf][0], bh[nf][1]);
                    mma_bf16(acc[mf][nf], ah[mf], bl[nf][0], bl[nf][1]);
                    mma_bf16(acc[mf][nf], al[mf], bh[nf][0], bh[nf][1]);
                }
        }
        __syncthreads();
    }

    #pragma unroll
    for (int mf = 0; mf < 2; mf++) {
        #pragma unroll
        for (int e = 0; e < 2; e++) {
            int row = m0 + wm + mf * 16 + g + e * 8;
            #pragma unroll
            for (int nf = 0; nf < 4; nf++) {
                int col = j0 + wn + nf * 8 + 2 * j;
                float v0 = (acc[mf][nf][e * 2 + 0] + bias[col])     * oscale;
                float v1 = (acc[mf][nf][e * 2 + 1] + bias[col + 1]) * oscale;
                if (ROUND) {
                    v0 = __uint_as_float(f2tf32(v0));
                    v1 = __uint_as_float(f2tf32(v1));
                }
                float2 val = make_float2(v0, v1);
                if (HEAD_MAJOR) {
                    int bb = row >> 11, n = row & (N_ - 1);
                    int d  = col - j0;
                    *reinterpret_cast<float2*>(
                        &out[(((size_t)bb * H_ + blockIdx.x) * N_ + n) * 64 + d]) = val;
                } else {
                    *reinterpret_cast<float2*>(&out[(size_t)row * 1024 + col]) = val;
                }
            }
        }
    }
}

// --------------------- register-resident flash attention --------------------
// Block 128 thr (4 warps), q-tile 64 (warp owns 16 rows), key-tile 64.
// smem floats: Ks[2][64][68] @0 | Vs[2][64][72] @8704 | Ps[4][16][68] @17920.
// Epilogue writes the attn output directly as bf16 hi/lo split planes.
__global__ __launch_bounds__(128, 2)
void attn_kernel(const float* __restrict__ Qg, const float* __restrict__ Kg,
                 const float* __restrict__ Vg, const float* __restrict__ bias,
                 __nv_bfloat16* __restrict__ Ohi)
{
    extern __shared__ __align__(16) float sf[];
    const int tid  = threadIdx.x;
    const int lane = tid & 31, warp = tid >> 5;
    const int g    = lane >> 2, j = lane & 3;
    const int q0   = blockIdx.x * 64, h = blockIdx.y, b = blockIdx.z;
    const size_t bh = ((size_t)b * H_ + h) * N_;
    const int wq   = warp * 16;
    float* Psw = sf + 17920 + warp * 1088;
    const unsigned sbase = s_u32(sf);
    __nv_bfloat16* Olo = Ohi + (size_t)4096 * 1024;

    // Q fragments (tf32-rounded & pre-scaled by 1/8 in proj epilogue)
    unsigned qa[8][4];
    {
        const float* q0p = Qg + (bh + q0 + wq + g) * 64;
        const float* q1p = q0p + 8 * 64;
        #pragma unroll
        for (int dk = 0; dk < 8; dk++) {
            qa[dk][0] = __float_as_uint(q0p[dk * 8 + j]);
            qa[dk][1] = __float_as_uint(q1p[dk * 8 + j]);
            qa[dk][2] = __float_as_uint(q0p[dk * 8 + j + 4]);
            qa[dk][3] = __float_as_uint(q1p[dk * 8 + j + 4]);
        }
    }

    float Oa[8][4];
    #pragma unroll
    for (int nb = 0; nb < 8; nb++)
        #pragma unroll
        for (int e = 0; e < 4; e++) Oa[nb][e] = 0.0f;
    float m0r = -1e30f, m1r = -1e30f, l0 = 0.0f, l1 = 0.0f;

    auto issue_kv = [&](int k0, int stg) {
        unsigned kbase = sbase + (unsigned)(stg * 4352) * 4u;
        unsigned vbase = sbase + (unsigned)(8704 + stg * 4608) * 4u;
        const float* Kp = Kg + (bh + k0) * 64;
        const float* Vp = Vg + (bh + k0) * 64;
        #pragma unroll
        for (int i = 0; i < 8; i++) {
            int c = tid + i * 128;
            int r = c >> 4, cc = (c & 15) * 4;
            cp16(kbase + (unsigned)(r * 68 + cc) * 4u, Kp + r * 64 + cc);
            cp16(vbase + (unsigned)(r * 72 + cc) * 4u, Vp + r * 64 + cc);
        }
    };

    issue_kv(0, 0);
    CP_COMMIT();

    const float* bb0 = bias + ((size_t)h * N_ + q0 + wq + g) * N_;
    const float* bb1 = bb0 + (size_t)8 * N_;

    for (int t = 0; t < 32; t++) {
        if (t + 1 < 32) { issue_kv((t + 1) * 64, (t + 1) & 1); CP_COMMIT(); CP_WAIT1(); }
        else            { CP_WAIT0(); }
        __syncthreads();

        const float* Ks = sf + (t & 1) * 4352;
        const float* Vs = sf + 8704 + (t & 1) * 4608;
        const int kcol = t * 64;

        // Front-batch bias loads: issue all 16 LDGs before the mma block so
        // DRAM latency is covered by the QK^T tensor work (MLP up, stalls down).
        float2 bt0[8], bt1[8];
        #pragma unroll
        for (int nb = 0; nb < 8; nb++) {
            bt0[nb] = *reinterpret_cast<const float2*>(bb0 + kcol + nb * 8 + 2 * j);
            bt1[nb] = *reinterpret_cast<const float2*>(bb1 + kcol + nb * 8 + 2 * j);
        }

        // S = Q @ K^T
        float sa[8][4];
        #pragma unroll
        for (int nb = 0; nb < 8; nb++)
            #pragma unroll
            for (int e = 0; e < 4; e++) sa[nb][e] = 0.0f;
        #pragma unroll
        for (int dk = 0; dk < 8; dk++)
            #pragma unroll
            for (int nb = 0; nb < 8; nb++) {
                const float* kp = Ks + (nb * 8 + g) * 68 + dk * 8 + j;
                mma_tf32(sa[nb], qa[dk], __float_as_uint(kp[0]),
                                         __float_as_uint(kp[4]));
            }

        // bias + online softmax (register stats)
        float mx0 = -1e30f, mx1 = -1e30f;
        #pragma unroll
        for (int nb = 0; nb < 8; nb++) {
            sa[nb][0] += bt0[nb].x; sa[nb][1] += bt0[nb].y;
            sa[nb][2] += bt1[nb].x; sa[nb][3] += bt1[nb].y;
            mx0 = fmaxf(mx0, fmaxf(sa[nb][0], sa[nb][1]));
            mx1 = fmaxf(mx1, fmaxf(sa[nb][2], sa[nb][3]));
        }
        mx0 = fmaxf(mx0, __shfl_xor_sync(0xffffffffu, mx0, 1));
        mx0 = fmaxf(mx0, __shfl_xor_sync(0xffffffffu, mx0, 2));
        mx1 = fmaxf(mx1, __shfl_xor_sync(0xffffffffu, mx1, 1));
        mx1 = fmaxf(mx1, __shfl_xor_sync(0xffffffffu, mx1, 2));
        float mn0 = fmaxf(m0r, mx0), mn1 = fmaxf(m1r, mx1);
        float al0 = __expf(m0r - mn0), al1 = __expf(m1r - mn1);
        m0r = mn0; m1r = mn1;

        __syncwarp();
        float s0 = 0.0f, s1 = 0.0f;
        #pragma unroll
        for (int nb = 0; nb < 8; nb++) {
            float p0 = __expf(sa[nb][0] - mn0);
            float p1 = __expf(sa[nb][1] - mn0);
            float p2 = __expf(sa[nb][2] - mn1);
            float p3 = __expf(sa[nb][3] - mn1);
            s0 += p0 + p1; s1 += p2 + p3;
            Psw[g * 68 + nb * 8 + 2 * j]           = __uint_as_float(f2tf32(p0));
            Psw[g * 68 + nb * 8 + 2 * j + 1]       = __uint_as_float(f2tf32(p1));
            Psw[(g + 8) * 68 + nb * 8 + 2 * j]     = __uint_as_float(f2tf32(p2));
            Psw[(g + 8) * 68 + nb * 8 + 2 * j + 1] = __uint_as_float(f2tf32(p3));
            Oa[nb][0] *= al0; Oa[nb][1] *= al0;
            Oa[nb][2] *= al1; Oa[nb][3] *= al1;
        }
        s0 += __shfl_xor_sync(0xffffffffu, s0, 1);
        s0 += __shfl_xor_sync(0xffffffffu, s0, 2);
        s1 += __shfl_xor_sync(0xffffffffu, s1, 1);
        s1 += __shfl_xor_sync(0xffffffffu, s1, 2);
        l0 = l0 * al0 + s0;
        l1 = l1 * al1 + s1;
        __syncwarp();

        // O += P @ V
        #pragma unroll
        for (int kk = 0; kk < 8; kk++) {
            unsigned pa[4];
            pa[0] = __float_as_uint(Psw[g * 68 + kk * 8 + j]);
            pa[1] = __float_as_uint(Psw[(g + 8) * 68 + kk * 8 + j]);
            pa[2] = __float_as_uint(Psw[g * 68 + kk * 8 + j + 4]);
            pa[3] = __float_as_uint(Psw[(g + 8) * 68 + kk * 8 + j + 4]);
            #pragma unroll
            for (int nb = 0; nb < 8; nb++) {
                const float* vp = Vs + (kk * 8 + j) * 72 + nb * 8 + g;
                mma_tf32(Oa[nb], pa, __float_as_uint(vp[0]),
                                     __float_as_uint(vp[4 * 72]));
            }
        }
        __syncthreads();  // release this K/V stage before it is overwritten
    }

    // Epilogue: normalize and write bf16 hi/lo split planes directly
    // (feeds the O-projection GEMM; removes the separate split pass).
    const float li0 = 1.0f / l0, li1 = 1.0f / l1;
    const size_t row0 = ((size_t)b * N_ + q0 + wq + g) * 1024;
    const size_t row1 = row0 + (size_t)8 * 1024;
    #pragma unroll
    for (int nb = 0; nb < 8; nb++) {
        const size_t c = (size_t)h * 64 + nb * 8 + 2 * j;
        float v0 = Oa[nb][0] * li0, v1 = Oa[nb][1] * li0;
        float v2 = Oa[nb][2] * li1, v3 = Oa[nb][3] * li1;
        __nv_bfloat16 h0 = __float2bfloat16_rn(v0);
        __nv_bfloat16 h1 = __float2bfloat16_rn(v1);
        __nv_bfloat16 h2 = __float2bfloat16_rn(v2);
        __nv_bfloat16 h3 = __float2bfloat16_rn(v3);
        __nv_bfloat16 e0 = __float2bfloat16_rn(v0 - __bfloat162float(h0));
        __nv_bfloat16 e1 = __float2bfloat16_rn(v1 - __bfloat162float(h1));
        __nv_bfloat16 e2 = __float2bfloat16_rn(v2 - __bfloat162float(h2));
        __nv_bfloat16 e3 = __float2bfloat16_rn(v3 - __bfloat162float(h3));
        *reinterpret_cast<__nv_bfloat162*>(Ohi + row0 + c) = __halves2bfloat162(h0, h1);
        *reinterpret_cast<__nv_bfloat162*>(Ohi + row1 + c) = __halves2bfloat162(h2, h3);
        *reinterpret_cast<__nv_bfloat162*>(Olo + row0 + c) = __halves2bfloat162(e0, e1);
        *reinterpret_cast<__nv_bfloat162*>(Olo + row1 + c) = __halves2bfloat162(e2, e3);
    }
}

// --------------------------------- launcher ---------------------------------
extern "C" void kernel_launch(void* const* d_in, const int* in_sizes, int n_in,
                              void* d_out, int out_size)
{
    (void)in_sizes; (void)n_in; (void)out_size;
    const float* x    = (const float*)d_in[0];
    const float* ctx  = (const float*)d_in[1];
    const float* bias = (const float*)d_in[2];
    const float* Wq   = (const float*)d_in[3];
    const float* bq   = (const float*)d_in[4];
    const float* Wk   = (const float*)d_in[5];
    const float* bk   = (const float*)d_in[6];
    const float* Wv   = (const float*)d_in[7];
    const float* bv   = (const float*)d_in[8];
    const float* Wo   = (const float*)d_in[9];
    const float* bo   = (const float*)d_in[10];
    float* out = (float*)d_out;

    float *qp, *kp, *vp;
    __nv_bfloat16 *xs, *cs, *os, *ws;
    cudaGetSymbolAddress((void**)&qp, g_Q);
    cudaGetSymbolAddress((void**)&kp, g_K);
    cudaGetSymbolAddress((void**)&vp, g_V);
    cudaGetSymbolAddress((void**)&xs, g_Xs);
    cudaGetSymbolAddress((void**)&cs, g_Cs);
    cudaGetSymbolAddress((void**)&os, g_Os);
    cudaGetSymbolAddress((void**)&ws, g_Ws);

    const int proj_smem = 7680 * 2 * 4;   // 61,440 B
    const int attn_smem = 22272 * 4;      // 89,088 B
    cudaFuncSetAttribute(proj_bf16_kernel<true , true >,
        cudaFuncAttributeMaxDynamicSharedMemorySize, proj_smem);
    cudaFuncSetAttribute(proj_bf16_kernel<false, false>,
        cudaFuncAttributeMaxDynamicSharedMemorySize, proj_smem);
    cudaFuncSetAttribute(attn_kernel,
        cudaFuncAttributeMaxDynamicSharedMemorySize, attn_smem);
    // Ask for the full 228KB smem carveout so 2 CTAs/SM actually co-reside.
    cudaFuncSetAttribute(proj_bf16_kernel<true , true >,
        cudaFuncAttributePreferredSharedMemoryCarveout, 100);
    cudaFuncSetAttribute(proj_bf16_kernel<false, false>,
        cudaFuncAttributePreferredSharedMemoryCarveout, 100);
    cudaFuncSetAttribute(attn_kernel,
        cudaFuncAttributePreferredSharedMemoryCarveout, 100);

    const size_t WPITCH = (size_t)2 * 1024 * 1024;  // hi+lo plane per weight

    // 1) all splits in one launch
    split_all_kernel<<<12288, 256>>>(x, ctx, Wq, Wk, Wv, Wo, xs, cs, ws);

    // 2) merged Q/K/V projections (gridDim.z = 3)
    ProjArgs pa;
    pa.A[0] = xs; pa.Wp[0] = ws + 0 * WPITCH; pa.bias[0] = bq; pa.out[0] = qp; pa.scale[0] = 0.125f;
    pa.A[1] = cs; pa.Wp[1] = ws + 1 * WPITCH; pa.bias[1] = bk; pa.out[1] = kp; pa.scale[1] = 1.0f;
    pa.A[2] = cs; pa.Wp[2] = ws + 2 * WPITCH; pa.bias[2] = bv; pa.out[2] = vp; pa.scale[2] = 1.0f;
    dim3 gp(16, 32, 3);   // (C/64, 4096/128, QKV)
    proj_bf16_kernel<true , true ><<<gp, 256, proj_smem>>>(pa);

    // 3) attention (writes bf16 split planes directly)
    dim3 ga(N_ / 64, H_, B_);   // (32, 16, 2)
    attn_kernel<<<ga, 128, attn_smem>>>(qp, kp, vp, bias, os);

    // 4) output projection
    ProjArgs po;
    po.A[0] = os; po.Wp[0] = ws + 3 * WPITCH; po.bias[0] = bo; po.out[0] = out; po.scale[0] = 1.0f;
    po.A[1] = po.A[0]; po.Wp[1] = po.Wp[0]; po.bias[1] = po.bias[0]; po.out[1] = po.out[0]; po.scale[1] = 1.0f;
    po.A[2] = po.A[0]; po.Wp[2] = po.Wp[0]; po.bias[2] = po.bias[0]; po.out[2] = po.out[0]; po.scale[2] = 1.0f;
    dim3 go(16, 32, 1);
    proj_bf16_kernel<false, false><<<go, 256, proj_smem>>>(po);
}

// round 11
// speedup vs baseline: 1.0467x; 1.0013x over previous
#include <cuda_runtime.h>
#include <cuda_bf16.h>
#include <cstdint>

#define B_ 2
#define N_ 2048
#define C_ 1024
#define H_ 16
#define D_ 64

// ------------------------- scratch (__device__ globals) ----------------------
__device__ float g_Q[(size_t)B_*H_*N_*D_];   // tf32-rounded, pre-scaled by 1/8
__device__ float g_K[(size_t)B_*H_*N_*D_];   // tf32-rounded
__device__ float g_V[(size_t)B_*H_*N_*D_];   // tf32-rounded

__device__ __nv_bfloat16 g_Xs[2u*4096u*1024u];    // x   split: hi plane, lo plane
__device__ __nv_bfloat16 g_Cs[2u*4096u*1024u];    // ctx split
__device__ __nv_bfloat16 g_Os[2u*4096u*1024u];    // attn-out split (written by attn)
__device__ __nv_bfloat16 g_Ws[4u*2u*1024u*1024u]; // 4 weights x (hi, lo)

// ------------------------------- PTX helpers --------------------------------
__device__ __forceinline__ unsigned f2tf32(float f) {
    unsigned o; asm("cvt.rna.tf32.f32 %0, %1;" : "=r"(o) : "f"(f)); return o;
}
__device__ __forceinline__ void mma_tf32(float c[4], const unsigned a[4],
                                         unsigned b0, unsigned b1) {
    asm volatile("mma.sync.aligned.m16n8k8.row.col.f32.tf32.tf32.f32 "
        "{%0,%1,%2,%3}, {%4,%5,%6,%7}, {%8,%9}, {%0,%1,%2,%3};"
        : "+f"(c[0]), "+f"(c[1]), "+f"(c[2]), "+f"(c[3])
        : "r"(a[0]), "r"(a[1]), "r"(a[2]), "r"(a[3]), "r"(b0), "r"(b1));
}
__device__ __forceinline__ void mma_bf16(float c[4], const unsigned a[4],
                                         unsigned b0, unsigned b1) {
    asm volatile("mma.sync.aligned.m16n8k16.row.col.f32.bf16.bf16.f32 "
        "{%0,%1,%2,%3}, {%4,%5,%6,%7}, {%8,%9}, {%0,%1,%2,%3};"
        : "+f"(c[0]), "+f"(c[1]), "+f"(c[2]), "+f"(c[3])
        : "r"(a[0]), "r"(a[1]), "r"(a[2]), "r"(a[3]), "r"(b0), "r"(b1));
}
__device__ __forceinline__ void cp16(unsigned dst, const void* src) {
    asm volatile("cp.async.cg.shared.global [%0], [%1], 16;" :: "r"(dst), "l"(src));
}
#define CP_COMMIT() asm volatile("cp.async.commit_group;")
#define CP_WAIT1()  asm volatile("cp.async.wait_group 1;")
#define CP_WAIT0()  asm volatile("cp.async.wait_group 0;")
__device__ __forceinline__ unsigned s_u32(const void* p) {
    return (unsigned)__cvta_generic_to_shared(p);
}

// ----------------------- merged bf16 hi/lo split kernel ---------------------
// One launch splits x, ctx, and the 4 weight matrices.
// Grid: [0,4096) x | [4096,8192) ctx | [8192,12288) weights (1024 blocks each).
__global__ __launch_bounds__(256)
void split_all_kernel(const float* __restrict__ x, const float* __restrict__ ctx,
                      const float* __restrict__ Wq, const float* __restrict__ Wk,
                      const float* __restrict__ Wv, const float* __restrict__ Wo,
                      __nv_bfloat16* __restrict__ xs, __nv_bfloat16* __restrict__ cs,
                      __nv_bfloat16* __restrict__ ws)
{
    int blk = blockIdx.x;
    const float* src;
    __nv_bfloat16* dst;
    int n4;
    if (blk < 4096)      { src = x;   dst = xs; n4 = 1048576; }
    else if (blk < 8192) { src = ctx; dst = cs; n4 = 1048576; blk -= 4096; }
    else {
        int w = (blk - 8192) >> 10;
        blk = (blk - 8192) & 1023;
        n4 = 262144;
        src = (w == 0) ? Wq : (w == 1) ? Wk : (w == 2) ? Wv : Wo;
        dst = ws + (size_t)w * 2097152u;
    }
    int i = blk * 256 + threadIdx.x;
    if (i >= n4) return;
    float4 v = reinterpret_cast<const float4*>(src)[i];
    __nv_bfloat16 h0 = __float2bfloat16_rn(v.x);
    __nv_bfloat16 h1 = __float2bfloat16_rn(v.y);
    __nv_bfloat16 h2 = __float2bfloat16_rn(v.z);
    __nv_bfloat16 h3 = __float2bfloat16_rn(v.w);
    __nv_bfloat16 l0 = __float2bfloat16_rn(v.x - __bfloat162float(h0));
    __nv_bfloat16 l1 = __float2bfloat16_rn(v.y - __bfloat162float(h1));
    __nv_bfloat16 l2 = __float2bfloat16_rn(v.z - __bfloat162float(h2));
    __nv_bfloat16 l3 = __float2bfloat16_rn(v.w - __bfloat162float(h3));
    __nv_bfloat162* hi2 = reinterpret_cast<__nv_bfloat162*>(dst);
    __nv_bfloat162* lo2 = reinterpret_cast<__nv_bfloat162*>(dst + (size_t)n4 * 4);
    hi2[2*i+0] = __halves2bfloat162(h0, h1);
    hi2[2*i+1] = __halves2bfloat162(h2, h3);
    lo2[2*i+0] = __halves2bfloat162(l0, l1);
    lo2[2*i+1] = __halves2bfloat162(l2, l3);
}

// ---------------------- bf16 3-term split GEMM (proj) -----------------------
// out[M=4096, 1024] = A @ W^T + bias.  A/W pre-split into bf16 hi/lo planes.
// Block: 256 thr (8 warps: 4m x 2n), tile 128x64, BK=32, cp.async 2 stages.
// blockIdx.z selects one of up to 3 problem instances (merged Q/K/V).
struct ProjArgs {
    const __nv_bfloat16* A[3];
    const __nv_bfloat16* Wp[3];
    const float* bias[3];
    float* out[3];
    float scale[3];
};

template<bool HEAD_MAJOR, bool ROUND>
__global__ __launch_bounds__(256, 2)
void proj_bf16_kernel(ProjArgs args)
{
    extern __shared__ __align__(16) unsigned sm32[];
    const int z = blockIdx.z;
    const __nv_bfloat16* A = args.A[z];
    const __nv_bfloat16* W = args.Wp[z];
    const float* bias      = args.bias[z];
    float* out             = args.out[z];
    const float oscale     = args.scale[z];

    const int tid  = threadIdx.x;
    const int lane = tid & 31, warp = tid >> 5;
    const int wm   = (warp >> 1) * 32, wn = (warp & 1) * 32;
    const int g    = lane >> 2, j = lane & 3;
    const int m0   = blockIdx.y * 128, j0 = blockIdx.x * 64;

    const __nv_bfloat16* Apl0 = A;
    const __nv_bfloat16* Apl1 = A + (size_t)4096 * 1024;
    const __nv_bfloat16* Wpl0 = W;
    const __nv_bfloat16* Wpl1 = W + (size_t)1024 * 1024;
    const unsigned sbase = s_u32(sm32);

    float acc[2][4][4];
    #pragma unroll
    for (int a = 0; a < 2; a++)
        #pragma unroll
        for (int b = 0; b < 4; b++)
            #pragma unroll
            for (int c = 0; c < 4; c++) acc[a][b][c] = 0.0f;

    auto issue_tile = [&](int kt, int stg) {
        unsigned base = sbase + (unsigned)stg * 7680u * 4u;
        #pragma unroll
        for (int i = 0; i < 4; i++) {                 // A: 1024 x 16B
            int c  = tid + i * 256;
            int pl = c >> 9, rem = c & 511, r = rem >> 2, q = rem & 3;
            const __nv_bfloat16* src = (pl ? Apl1 : Apl0) +
                (size_t)(m0 + r) * 1024 + kt + q * 8;
            cp16(base + (unsigned)(pl * 2560 + r * 20 + q * 4) * 4u, src);
        }
        #pragma unroll
        for (int i = 0; i < 2; i++) {                 // B: 512 x 16B
            int c  = tid + i * 256;
            int pl = c >> 8, rem = c & 255, r = rem >> 2, q = rem & 3;
            const __nv_bfloat16* src = (pl ? Wpl1 : Wpl0) +
                (size_t)(j0 + r) * 1024 + kt + q * 8;
            cp16(base + (unsigned)(5120 + pl * 1280 + r * 20 + q * 4) * 4u, src);
        }
    };

    issue_tile(0, 0);
    CP_COMMIT();

    for (int t = 0; t < 32; t++) {
        if (t + 1 < 32) { issue_tile((t + 1) * 32, (t + 1) & 1); CP_COMMIT(); CP_WAIT1(); }
        else            { CP_WAIT0(); }
        __syncthreads();

        const unsigned* S = sm32 + (t & 1) * 7680;
        #pragma unroll
        for (int ks = 0; ks < 2; ks++) {
            unsigned ah[2][4], al[2][4], bh[4][2], bl[4][2];
            #pragma unroll
            for (int mf = 0; mf < 2; mf++) {
                int rb = (wm + mf * 16 + g) * 20 + ks * 8 + j;
                ah[mf][0] = S[rb];            ah[mf][1] = S[rb + 160];
                ah[mf][2] = S[rb + 4];        ah[mf][3] = S[rb + 164];
                al[mf][0] = S[2560 + rb];     al[mf][1] = S[2560 + rb + 160];
                al[mf][2] = S[2560 + rb + 4]; al[mf][3] = S[2560 + rb + 164];
            }
            #pragma unroll
            for (int nf = 0; nf < 4; nf++) {
                int rb = 5120 + (wn + nf * 8 + g) * 20 + ks * 8 + j;
                bh[nf][0] = S[rb];        bh[nf][1] = S[rb + 4];
                bl[nf][0] = S[rb + 1280]; bl[nf][1] = S[rb + 1284];
            }
            #pragma unroll
            for (int mf = 0; mf < 2; mf++)
                #pragma unroll
                for (int nf = 0; nf < 4; nf++) {
                    mma_bf16(acc[mf][nf], ah[mf], bh[nf][0], bh[nf][1]);
                    mma_bf16(acc[mf][nf], ah[mf], bl[nf][0], bl[nf][1]);
                    mma_bf16(acc[mf][nf], al[mf], bh[nf][0], bh[nf][1]);
                }
        }
        __syncthreads();
    }

    #pragma unroll
    for (int mf = 0; mf < 2; mf++) {
        #pragma unroll
        for (int e = 0; e < 2; e++) {
            int row = m0 + wm + mf * 16 + g + e * 8;
            #pragma unroll
            for (int nf = 0; nf < 4; nf++) {
                int col = j0 + wn + nf * 8 + 2 * j;
                float v0 = (acc[mf][nf][e * 2 + 0] + bias[col])     * oscale;
                float v1 = (acc[mf][nf][e * 2 + 1] + bias[col + 1]) * oscale;
                if (ROUND) {
                    v0 = __uint_as_float(f2tf32(v0));
                    v1 = __uint_as_float(f2tf32(v1));
                }
                float2 val = make_float2(v0, v1);
                if (HEAD_MAJOR) {
                    int bb = row >> 11, n = row & (N_ - 1);
                    int d  = col - j0;
                    *reinterpret_cast<float2*>(
                        &out[(((size_t)bb * H_ + blockIdx.x) * N_ + n) * 64 + d]) = val;
                } else {
                    *reinterpret_cast<float2*>(&out[(size_t)row * 1024 + col]) = val;
                }
            }
        }
    }
}

// --------------------- register-resident flash attention --------------------
// Block 128 thr (4 warps), q-tile 64 (warp owns 16 rows), key-tile 64.
// smem floats: Ks[2][64][68] @0 | Vs[2][64][72] @8704 | Ps[4][16][68] @17920.
// Epilogue writes the attn output directly as bf16 hi/lo split planes.
__global__ __launch_bounds__(128, 2)
void attn_kernel(const float* __restrict__ Qg, const float* __restrict__ Kg,
                 const float* __restrict__ Vg, const float* __restrict__ bias,
                 __nv_bfloat16* __restrict__ Ohi)
{
    extern __shared__ __align__(16) float sf[];
    const int tid  = threadIdx.x;
    const int lane = tid & 31, warp = tid >> 5;
    const int g    = lane >> 2, j = lane & 3;
    const int q0   = blockIdx.x * 64, h = blockIdx.y, b = blockIdx.z;
    const size_t bh = ((size_t)b * H_ + h) * N_;
    const int wq   = warp * 16;
    float* Psw = sf + 17920 + warp * 1088;
    const unsigned sbase = s_u32(sf);
    __nv_bfloat16* Olo = Ohi + (size_t)4096 * 1024;

    // Q fragments (tf32-rounded & pre-scaled by 1/8 in proj epilogue)
    unsigned qa[8][4];
    {
        const float* q0p = Qg + (bh + q0 + wq + g) * 64;
        const float* q1p = q0p + 8 * 64;
        #pragma unroll
        for (int dk = 0; dk < 8; dk++) {
            qa[dk][0] = __float_as_uint(q0p[dk * 8 + j]);
            qa[dk][1] = __float_as_uint(q1p[dk * 8 + j]);
            qa[dk][2] = __float_as_uint(q0p[dk * 8 + j + 4]);
            qa[dk][3] = __float_as_uint(q1p[dk * 8 + j + 4]);
        }
    }

    float Oa[8][4];
    #pragma unroll
    for (int nb = 0; nb < 8; nb++)
        #pragma unroll
        for (int e = 0; e < 4; e++) Oa[nb][e] = 0.0f;
    float m0r = -1e30f, m1r = -1e30f, l0 = 0.0f, l1 = 0.0f;

    auto issue_kv = [&](int k0, int stg) {
        unsigned kbase = sbase + (unsigned)(stg * 4352) * 4u;
        unsigned vbase = sbase + (unsigned)(8704 + stg * 4608) * 4u;
        const float* Kp = Kg + (bh + k0) * 64;
        const float* Vp = Vg + (bh + k0) * 64;
        #pragma unroll
        for (int i = 0; i < 8; i++) {
            int c = tid + i * 128;
            int r = c >> 4, cc = (c & 15) * 4;
            cp16(kbase + (unsigned)(r * 68 + cc) * 4u, Kp + r * 64 + cc);
            cp16(vbase + (unsigned)(r * 72 + cc) * 4u, Vp + r * 64 + cc);
        }
    };

    issue_kv(0, 0);
    CP_COMMIT();

    const float* bb0 = bias + ((size_t)h * N_ + q0 + wq + g) * N_;
    const float* bb1 = bb0 + (size_t)8 * N_;

    for (int t = 0; t < 32; t++) {
        if (t + 1 < 32) { issue_kv((t + 1) * 64, (t + 1) & 1); CP_COMMIT(); CP_WAIT1(); }
        else            { CP_WAIT0(); }
        __syncthreads();

        const float* Ks = sf + (t & 1) * 4352;
        const float* Vs = sf + 8704 + (t & 1) * 4608;
        const int kcol = t * 64;

        // Front-batch bias loads: issue all 16 LDGs before the mma block so
        // DRAM latency is covered by the QK^T tensor work (MLP up, stalls down).
        float2 bt0[8], bt1[8];
        #pragma unroll
        for (int nb = 0; nb < 8; nb++) {
            bt0[nb] = *reinterpret_cast<const float2*>(bb0 + kcol + nb * 8 + 2 * j);
            bt1[nb] = *reinterpret_cast<const float2*>(bb1 + kcol + nb * 8 + 2 * j);
        }

        // S = Q @ K^T
        float sa[8][4];
        #pragma unroll
        for (int nb = 0; nb < 8; nb++)
            #pragma unroll
            for (int e = 0; e < 4; e++) sa[nb][e] = 0.0f;
        #pragma unroll
        for (int dk = 0; dk < 8; dk++)
            #pragma unroll
            for (int nb = 0; nb < 8; nb++) {
                const float* kp = Ks + (nb * 8 + g) * 68 + dk * 8 + j;
                mma_tf32(sa[nb], qa[dk], __float_as_uint(kp[0]),
                                         __float_as_uint(kp[4]));
            }

        // bias + online softmax (register stats)
        float mx0 = -1e30f, mx1 = -1e30f;
        #pragma unroll
        for (int nb = 0; nb < 8; nb++) {
            sa[nb][0] += bt0[nb].x; sa[nb][1] += bt0[nb].y;
            sa[nb][2] += bt1[nb].x; sa[nb][3] += bt1[nb].y;
            mx0 = fmaxf(mx0, fmaxf(sa[nb][0], sa[nb][1]));
            mx1 = fmaxf(mx1, fmaxf(sa[nb][2], sa[nb][3]));
        }
        mx0 = fmaxf(mx0, __shfl_xor_sync(0xffffffffu, mx0, 1));
        mx0 = fmaxf(mx0, __shfl_xor_sync(0xffffffffu, mx0, 2));
        mx1 = fmaxf(mx1, __shfl_xor_sync(0xffffffffu, mx1, 1));
        mx1 = fmaxf(mx1, __shfl_xor_sync(0xffffffffu, mx1, 2));
        float mn0 = fmaxf(m0r, mx0), mn1 = fmaxf(m1r, mx1);
        float al0 = __expf(m0r - mn0), al1 = __expf(m1r - mn1);
        m0r = mn0; m1r = mn1;

        __syncwarp();
        float s0 = 0.0f, s1 = 0.0f;
        #pragma unroll
        for (int nb = 0; nb < 8; nb++) {
            float p0 = __expf(sa[nb][0] - mn0);
            float p1 = __expf(sa[nb][1] - mn0);
            float p2 = __expf(sa[nb][2] - mn1);
            float p3 = __expf(sa[nb][3] - mn1);
            s0 += p0 + p1; s1 += p2 + p3;
            Psw[g * 68 + nb * 8 + 2 * j]           = __uint_as_float(f2tf32(p0));
            Psw[g * 68 + nb * 8 + 2 * j + 1]       = __uint_as_float(f2tf32(p1));
            Psw[(g + 8) * 68 + nb * 8 + 2 * j]     = __uint_as_float(f2tf32(p2));
            Psw[(g + 8) * 68 + nb * 8 + 2 * j + 1] = __uint_as_float(f2tf32(p3));
            Oa[nb][0] *= al0; Oa[nb][1] *= al0;
            Oa[nb][2] *= al1; Oa[nb][3] *= al1;
        }
        s0 += __shfl_xor_sync(0xffffffffu, s0, 1);
        s0 += __shfl_xor_sync(0xffffffffu, s0, 2);
        s1 += __shfl_xor_sync(0xffffffffu, s1, 1);
        s1 += __shfl_xor_sync(0xffffffffu, s1, 2);
        l0 = l0 * al0 + s0;
        l1 = l1 * al1 + s1;
        __syncwarp();

        // O += P @ V
        #pragma unroll
        for (int kk = 0; kk < 8; kk++) {
            unsigned pa[4];
            pa[0] = __float_as_uint(Psw[g * 68 + kk * 8 + j]);
            pa[1] = __float_as_uint(Psw[(g + 8) * 68 + kk * 8 + j]);
            pa[2] = __float_as_uint(Psw[g * 68 + kk * 8 + j + 4]);
            pa[3] = __float_as_uint(Psw[(g + 8) * 68 + kk * 8 + j + 4]);
            #pragma unroll
            for (int nb = 0; nb < 8; nb++) {
                const float* vp = Vs + (kk * 8 + j) * 72 + nb * 8 + g;
                mma_tf32(Oa[nb], pa, __float_as_uint(vp[0]),
                                     __float_as_uint(vp[4 * 72]));
            }
        }
        __syncthreads();  // release this K/V stage before it is overwritten
    }

    // Epilogue: normalize and write bf16 hi/lo split planes directly
    // (feeds the O-projection GEMM; removes the separate split pass).
    const float li0 = 1.0f / l0, li1 = 1.0f / l1;
    const size_t row0 = ((size_t)b * N_ + q0 + wq + g) * 1024;
    const size_t row1 = row0 + (size_t)8 * 1024;
    #pragma unroll
    for (int nb = 0; nb < 8; nb++) {
        const size_t c = (size_t)h * 64 + nb * 8 + 2 * j;
        float v0 = Oa[nb][0] * li0, v1 = Oa[nb][1] * li0;
        float v2 = Oa[nb][2] * li1, v3 = Oa[nb][3] * li1;
        __nv_bfloat16 h0 = __float2bfloat16_rn(v0);
        __nv_bfloat16 h1 = __float2bfloat16_rn(v1);
        __nv_bfloat16 h2 = __float2bfloat16_rn(v2);
        __nv_bfloat16 h3 = __float2bfloat16_rn(v3);
        __nv_bfloat16 e0 = __float2bfloat16_rn(v0 - __bfloat162float(h0));
        __nv_bfloat16 e1 = __float2bfloat16_rn(v1 - __bfloat162float(h1));
        __nv_bfloat16 e2 = __float2bfloat16_rn(v2 - __bfloat162float(h2));
        __nv_bfloat16 e3 = __float2bfloat16_rn(v3 - __bfloat162float(h3));
        *reinterpret_cast<__nv_bfloat162*>(Ohi + row0 + c) = __halves2bfloat162(h0, h1);
        *reinterpret_cast<__nv_bfloat162*>(Ohi + row1 + c) = __halves2bfloat162(h2, h3);
        *reinterpret_cast<__nv_bfloat162*>(Olo + row0 + c) = __halves2bfloat162(e0, e1);
        *reinterpret_cast<__nv_bfloat162*>(Olo + row1 + c) = __halves2bfloat162(e2, e3);
    }
}

// --------------------------------- launcher ---------------------------------
extern "C" void kernel_launch(void* const* d_in, const int* in_sizes, int n_in,
                              void* d_out, int out_size)
{
    (void)in_sizes; (void)n_in; (void)out_size;
    const float* x    = (const float*)d_in[0];
    const float* ctx  = (const float*)d_in[1];
    const float* bias = (const float*)d_in[2];
    const float* Wq   = (const float*)d_in[3];
    const float* bq   = (const float*)d_in[4];
    const float* Wk   = (const float*)d_in[5];
    const float* bk   = (const float*)d_in[6];
    const float* Wv   = (const float*)d_in[7];
    const float* bv   = (const float*)d_in[8];
    const float* Wo   = (const float*)d_in[9];
    const float* bo   = (const float*)d_in[10];
    float* out = (float*)d_out;

    float *qp, *kp, *vp;
    __nv_bfloat16 *xs, *cs, *os, *ws;
    cudaGetSymbolAddress((void**)&qp, g_Q);
    cudaGetSymbolAddress((void**)&kp, g_K);
    cudaGetSymbolAddress((void**)&vp, g_V);
    cudaGetSymbolAddress((void**)&xs, g_Xs);
    cudaGetSymbolAddress((void**)&cs, g_Cs);
    cudaGetSymbolAddress((void**)&os, g_Os);
    cudaGetSymbolAddress((void**)&ws, g_Ws);

    const int proj_smem = 7680 * 2 * 4;   // 61,440 B
    const int attn_smem = 22272 * 4;      // 89,088 B
    cudaFuncSetAttribute(proj_bf16_kernel<true , true >,
        cudaFuncAttributeMaxDynamicSharedMemorySize, proj_smem);
    cudaFuncSetAttribute(proj_bf16_kernel<false, false>,
        cudaFuncAttributeMaxDynamicSharedMemorySize, proj_smem);
    cudaFuncSetAttribute(attn_kernel,
        cudaFuncAttributeMaxDynamicSharedMemorySize, attn_smem);
    // Ask for the full 228KB smem carveout so 2 CTAs/SM actually co-reside.
    cudaFuncSetAttribute(proj_bf16_kernel<true , true >,
        cudaFuncAttributePreferredSharedMemoryCarveout, 100);
    cudaFuncSetAttribute(proj_bf16_kernel<false, false>,
        cudaFuncAttributePreferredSharedMemoryCarveout, 100);
    cudaFuncSetAttribute(attn_kernel,
        cudaFuncAttributePreferredSharedMemoryCarveout, 100);

    const size_t WPITCH = (size_t)2 * 1024 * 1024;  // hi+lo plane per weight

    // 1) all splits in one launch
    split_all_kernel<<<12288, 256>>>(x, ctx, Wq, Wk, Wv, Wo, xs, cs, ws);

    // 2) merged Q/K/V projections (gridDim.z = 3)
    ProjArgs pa;
    pa.A[0] = xs; pa.Wp[0] = ws + 0 * WPITCH; pa.bias[0] = bq; pa.out[0] = qp; pa.scale[0] = 0.125f;
    pa.A[1] = cs; pa.Wp[1] = ws + 1 * WPITCH; pa.bias[1] = bk; pa.out[1] = kp; pa.scale[1] = 1.0f;
    pa.A[2] = cs; pa.Wp[2] = ws + 2 * WPITCH; pa.bias[2] = bv; pa.out[2] = vp; pa.scale[2] = 1.0f;
    dim3 gp(16, 32, 3);   // (C/64, 4096/128, QKV)
    proj_bf16_kernel<true , true ><<<gp, 256, proj_smem>>>(pa);

    // 3) attention (writes bf16 split planes directly)
    dim3 ga(N_ / 64, H_, B_);   // (32, 16, 2)
    attn_kernel<<<ga, 128, attn_smem>>>(qp, kp, vp, bias, os);

    // 4) output projection
    ProjArgs po;
    po.A[0] = os; po.Wp[0] = ws + 3 * WPITCH; po.bias[0] = bo; po.out[0] = out; po.scale[0] = 1.0f;
    po.A[1] = po.A[0]; po.Wp[1] = po.Wp[0]; po.bias[1] = po.bias[0]; po.out[1] = po.out[0]; po.scale[1] = 1.0f;
    po.A[2] = po.A[0]; po.Wp[2] = po.Wp[0]; po.bias[2] = po.bias[0]; po.out[2] = po.out[0]; po.scale[2] = 1.0f;
    dim3 go(16, 32, 1);
    proj_bf16_kernel<false, false><<<go, 256, proj_smem>>>(po);
}